// round 1
// baseline (speedup 1.0000x reference)
#include <cuda_runtime.h>

#define B_   2
#define S_   2048
#define E_   1024
#define H_   16
#define D_   64
#define NTOK (B_*S_)

// Scratch (static device globals — no allocations in kernel_launch)
__device__ float g_q[NTOK*E_];
__device__ float g_k[NTOK*E_];
__device__ float g_v[NTOK*E_];
__device__ float g_ctx[NTOK*E_];

// ---------------------------------------------------------------------------
// GEMM: C[N][E] = A[N][E] @ W[E][E]^T + bias   (both row-major, K-contiguous)
// 64x64 block tile, BK=16, 256 threads, 4x4 micro-tile per thread.
// ---------------------------------------------------------------------------
__global__ __launch_bounds__(256) void gemm_bias_kernel(
    const float* __restrict__ A,
    const float* __restrict__ W,
    const float* __restrict__ bias,
    float* __restrict__ C)
{
    __shared__ float As[16][65];   // [k][m], padded
    __shared__ float Ws[16][65];   // [k][n], padded

    const int bm = blockIdx.y * 64;
    const int bn = blockIdx.x * 64;
    const int tid = threadIdx.x;
    const int lr  = tid >> 2;          // 0..63 load row
    const int lc4 = (tid & 3) * 4;     // 0,4,8,12 load col group
    const int tm  = tid >> 4;          // 0..15
    const int tn  = tid & 15;          // 0..15

    float acc[4][4] = {};

    for (int k0 = 0; k0 < E_; k0 += 16) {
        float4 av = *(const float4*)&A[(bm + lr) * E_ + k0 + lc4];
        float4 wv = *(const float4*)&W[(bn + lr) * E_ + k0 + lc4];
        __syncthreads();
        As[lc4+0][lr] = av.x; As[lc4+1][lr] = av.y;
        As[lc4+2][lr] = av.z; As[lc4+3][lr] = av.w;
        Ws[lc4+0][lr] = wv.x; Ws[lc4+1][lr] = wv.y;
        Ws[lc4+2][lr] = wv.z; Ws[lc4+3][lr] = wv.w;
        __syncthreads();
        #pragma unroll
        for (int kk = 0; kk < 16; kk++) {
            float a[4], b[4];
            #pragma unroll
            for (int i = 0; i < 4; i++) a[i] = As[kk][tm*4 + i];
            #pragma unroll
            for (int j = 0; j < 4; j++) b[j] = Ws[kk][tn + 16*j];
            #pragma unroll
            for (int i = 0; i < 4; i++)
                #pragma unroll
                for (int j = 0; j < 4; j++)
                    acc[i][j] += a[i] * b[j];
        }
    }

    #pragma unroll
    for (int i = 0; i < 4; i++) {
        const int row = bm + tm*4 + i;
        #pragma unroll
        for (int j = 0; j < 4; j++) {
            const int col = bn + tn + 16*j;
            C[row * E_ + col] = acc[i][j] + bias[col];
        }
    }
}

// ---------------------------------------------------------------------------
// Fused attention with softmax over the HEADS axis.
// Block: 16 queries, 256 threads. Loop over 64-key tiles; within a k-tile:
//   - scores for all 16 heads (4 head-groups of 4), kept in smem
//   - softmax across the 16 heads per (q,k)
//   - PV accumulation into registers (64 accums/thread)
// Writes g_ctx[b][q][h*64+d]  (== transpose(0,2,1,3).reshape layout).
// ---------------------------------------------------------------------------
#define TQ     16
#define TK     64
#define QSTR   1028          // 1024 + 4 pad (floats)  -> conflict-free q reads
#define SSTR   68            // 64 + 4 pad             -> conflict-free s rw
#define KVSTR  65            // 64 + 1 pad             -> conflict-free kv reads
#define SQ_OFF  0
#define SS_OFF  (TQ*QSTR)                    // 16448
#define SKV_OFF (SS_OFF + H_*TQ*SSTR)        // 16448 + 17408 = 33856
#define SMEM_FLOATS (SKV_OFF + 4*TK*KVSTR)   // 33856 + 16640 = 50496
#define SMEM_BYTES  (SMEM_FLOATS * 4)        // 201984 B

__global__ __launch_bounds__(256, 1) void attn_kernel()
{
    extern __shared__ float smem[];
    float* sm_q  = smem + SQ_OFF;
    float* sm_s  = smem + SS_OFF;
    float* sm_kv = smem + SKV_OFF;

    const int b      = blockIdx.y;
    const int q_base = blockIdx.x * TQ;
    const int n_base = b * S_ + q_base;
    const int tid    = threadIdx.x;

    // Load all 16 queries (full E=1024) into smem, float4, coalesced.
    {
        const float4* src = (const float4*)&g_q[n_base * E_];
        #pragma unroll
        for (int it = 0; it < 16; it++) {
            int idx = tid + it * 256;          // 0..4095 float4
            int row = idx >> 8;                // 0..15
            int c4  = idx & 255;               // 0..255
            float4 v = src[row * 256 + c4];
            *(float4*)&sm_q[row * QSTR + c4 * 4] = v;
        }
    }

    // Thread mapping (fixed for whole kernel):
    const int hh = tid >> 6;      // head-in-group 0..3
    const int t64 = tid & 63;
    const int qt = t64 >> 4;      // q micro-tile 0..3 -> rows qt*4..+3
    const int kd = t64 & 15;      // k base (scores) / d base (PV); +16*j strided

    float o_acc[4][4][4] = {};    // [head-group][q][d-sub]

    for (int kt = 0; kt < S_ / TK; kt++) {
        const int kbase = b * S_ + kt * TK;

        // ----- scores: 4 head-groups of 4 heads -----
        #pragma unroll
        for (int hg = 0; hg < 4; hg++) {
            __syncthreads();   // sm_kv reuse / sm_s overwrite safety
            #pragma unroll
            for (int it = 0; it < 16; it++) {
                int idx = tid + it * 256;              // 0..4095 float4
                int d4 = idx & 15, k = (idx >> 4) & 63, lh = idx >> 10;
                float4 v = *(const float4*)&g_k[(kbase + k) * E_ + (hg*4 + lh) * 64 + d4*4];
                float* dst = &sm_kv[lh * (TK*KVSTR) + k * KVSTR + d4*4];
                dst[0] = v.x; dst[1] = v.y; dst[2] = v.z; dst[3] = v.w;
            }
            __syncthreads();

            const int h = hg * 4 + hh;
            float acc[4][4] = {};
            const float* qp = &sm_q[(qt*4) * QSTR + h * 64];
            const float* kp = &sm_kv[hh * (TK*KVSTR) + kd * KVSTR];
            #pragma unroll
            for (int d = 0; d < 64; d++) {
                float a[4], bb[4];
                #pragma unroll
                for (int i = 0; i < 4; i++) a[i]  = qp[i*QSTR + d];
                #pragma unroll
                for (int j = 0; j < 4; j++) bb[j] = kp[j*16*KVSTR + d];
                #pragma unroll
                for (int i = 0; i < 4; i++)
                    #pragma unroll
                    for (int j = 0; j < 4; j++)
                        acc[i][j] += a[i] * bb[j];
            }
            #pragma unroll
            for (int i = 0; i < 4; i++)
                #pragma unroll
                for (int j = 0; j < 4; j++)
                    sm_s[(h*16 + qt*4 + i) * SSTR + kd + 16*j] = acc[i][j] * 0.125f;
        }
        __syncthreads();

        // ----- softmax over the 16 heads per (q,k) pair -----
        #pragma unroll
        for (int pp = 0; pp < 4; pp++) {
            int p = tid + pp * 256;          // 0..1023
            int q = p >> 6, k = p & 63;
            float e[16]; float sum = 0.f;
            #pragma unroll
            for (int h = 0; h < 16; h++) {
                e[h] = __expf(sm_s[(h*16 + q) * SSTR + k]);
                sum += e[h];
            }
            float inv = 1.0f / sum;
            #pragma unroll
            for (int h = 0; h < 16; h++)
                sm_s[(h*16 + q) * SSTR + k] = e[h] * inv;
        }

        // ----- PV: 4 head-groups of 4 heads -----
        #pragma unroll
        for (int hg = 0; hg < 4; hg++) {
            __syncthreads();   // protect sm_s (softmax done) / sm_kv reuse
            #pragma unroll
            for (int it = 0; it < 16; it++) {
                int idx = tid + it * 256;
                int d4 = idx & 15, k = (idx >> 4) & 63, lh = idx >> 10;
                float4 v = *(const float4*)&g_v[(kbase + k) * E_ + (hg*4 + lh) * 64 + d4*4];
                float* dst = &sm_kv[lh * (TK*KVSTR) + k * KVSTR + d4*4];
                dst[0] = v.x; dst[1] = v.y; dst[2] = v.z; dst[3] = v.w;
            }
            __syncthreads();

            const int h = hg * 4 + hh;
            const float* sp = &sm_s[(h*16 + qt*4) * SSTR];
            const float* vp = &sm_kv[hh * (TK*KVSTR) + kd];
            #pragma unroll
            for (int k = 0; k < 64; k++) {
                float a[4], bb[4];
                #pragma unroll
                for (int i = 0; i < 4; i++) a[i]  = sp[i*SSTR + k];
                #pragma unroll
                for (int j = 0; j < 4; j++) bb[j] = vp[k*KVSTR + 16*j];
                #pragma unroll
                for (int i = 0; i < 4; i++)
                    #pragma unroll
                    for (int j = 0; j < 4; j++)
                        o_acc[hg][i][j] += a[i] * bb[j];
            }
        }
    }

    // ----- write context in [b][q][h*64+d] layout -----
    #pragma unroll
    for (int hg = 0; hg < 4; hg++) {
        const int h = hg * 4 + hh;
        #pragma unroll
        for (int i = 0; i < 4; i++) {
            const int n = n_base + qt*4 + i;
            #pragma unroll
            for (int j = 0; j < 4; j++)
                g_ctx[n * E_ + h*64 + kd + 16*j] = o_acc[hg][i][j];
        }
    }
}

// ---------------------------------------------------------------------------
extern "C" void kernel_launch(void* const* d_in, const int* in_sizes, int n_in,
                              void* d_out, int out_size)
{
    const float* x  = (const float*)d_in[0];
    const float* Wq = (const float*)d_in[1];
    const float* bq = (const float*)d_in[2];
    const float* Wk = (const float*)d_in[3];
    const float* bk = (const float*)d_in[4];
    const float* Wv = (const float*)d_in[5];
    const float* bv = (const float*)d_in[6];
    const float* Wo = (const float*)d_in[7];
    const float* bo = (const float*)d_in[8];
    float* out = (float*)d_out;

    float *gq, *gk, *gv, *gctx;
    cudaGetSymbolAddress((void**)&gq,   g_q);
    cudaGetSymbolAddress((void**)&gk,   g_k);
    cudaGetSymbolAddress((void**)&gv,   g_v);
    cudaGetSymbolAddress((void**)&gctx, g_ctx);

    cudaFuncSetAttribute(attn_kernel,
                         cudaFuncAttributeMaxDynamicSharedMemorySize, SMEM_BYTES);

    dim3 ggrid(E_ / 64, NTOK / 64);   // (16, 64)
    gemm_bias_kernel<<<ggrid, 256>>>(x, Wq, bq, gq);
    gemm_bias_kernel<<<ggrid, 256>>>(x, Wk, bk, gk);
    gemm_bias_kernel<<<ggrid, 256>>>(x, Wv, bv, gv);

    dim3 agrid(S_ / TQ, B_);          // (128, 2)
    attn_kernel<<<agrid, 256, SMEM_BYTES>>>();

    gemm_bias_kernel<<<ggrid, 256>>>(gctx, Wo, bo, out);
}

// round 3
// speedup vs baseline: 4.2150x; 4.2150x over previous
#include <cuda_runtime.h>
#include <cuda_bf16.h>
#include <cuda_fp16.h>
#include <cstdint>

#define B_   2
#define S_   2048
#define E_   1024
#define H_   16
#define D_   64
#define NTOK (B_*S_)

static constexpr long long SSLL = (long long)S_ * S_;                 // 4194304
static constexpr long long SCORES_ELEMS = (long long)B_ * H_ * SSLL;  // 134217728

// ---------------- static scratch ----------------
__device__ __nv_bfloat16 g_xhi[NTOK*E_], g_xlo[NTOK*E_];
__device__ __nv_bfloat16 g_whi[4*E_*E_], g_wlo[4*E_*E_];
__device__ __nv_bfloat16 g_qhi[NTOK*E_], g_qlo[NTOK*E_];
__device__ __nv_bfloat16 g_khi[NTOK*E_], g_klo[NTOK*E_];
__device__ float         g_vf [NTOK*E_];
__device__ __half        g_vt16[NTOK*E_];       // [b][e][k], e=h*64+d
__device__ float         g_sc [SCORES_ELEMS];   // scores fp32 [b,h,q,k]
__device__ __half        g_a16[SCORES_ELEMS];   // attn fp16
__device__ __nv_bfloat16 g_chi[NTOK*E_], g_clo[NTOK*E_];

// ---------------- asm helpers ----------------
__device__ __forceinline__ uint32_t smem_u32(const void* p) {
    uint32_t a;
    asm("{ .reg .u64 t; cvta.to.shared.u64 t, %1; cvt.u32.u64 %0, t; }" : "=r"(a) : "l"(p));
    return a;
}
__device__ __forceinline__ void cp16(uint32_t dst, const void* src) {
    asm volatile("cp.async.cg.shared.global [%0], [%1], 16;" :: "r"(dst), "l"(src));
}
__device__ __forceinline__ void cp_commit() { asm volatile("cp.async.commit_group;"); }
__device__ __forceinline__ void cp_wait1()  { asm volatile("cp.async.wait_group 1;"); }
__device__ __forceinline__ void ldsm4(uint32_t* r, uint32_t addr) {
    asm volatile("ldmatrix.sync.aligned.m8n8.x4.shared.b16 {%0,%1,%2,%3}, [%4];"
        : "=r"(r[0]), "=r"(r[1]), "=r"(r[2]), "=r"(r[3]) : "r"(addr));
}
__device__ __forceinline__ void mma_bf16(float* d, const uint32_t* a, const uint32_t* b) {
    asm volatile("mma.sync.aligned.m16n8k16.row.col.f32.bf16.bf16.f32 "
        "{%0,%1,%2,%3}, {%4,%5,%6,%7}, {%8,%9}, {%0,%1,%2,%3};"
        : "+f"(d[0]), "+f"(d[1]), "+f"(d[2]), "+f"(d[3])
        : "r"(a[0]), "r"(a[1]), "r"(a[2]), "r"(a[3]), "r"(b[0]), "r"(b[1]));
}
__device__ __forceinline__ void mma_f16(float* d, const uint32_t* a, const uint32_t* b) {
    asm volatile("mma.sync.aligned.m16n8k16.row.col.f32.f16.f16.f32 "
        "{%0,%1,%2,%3}, {%4,%5,%6,%7}, {%8,%9}, {%0,%1,%2,%3};"
        : "+f"(d[0]), "+f"(d[1]), "+f"(d[2]), "+f"(d[3])
        : "r"(a[0]), "r"(a[1]), "r"(a[2]), "r"(a[3]), "r"(b[0]), "r"(b[1]));
}

// ---------------- utility kernels ----------------
__global__ void split_kernel(const float* __restrict__ src,
                             __nv_bfloat16* __restrict__ hi,
                             __nv_bfloat16* __restrict__ lo, int n) {
    for (int i = blockIdx.x * 256 + threadIdx.x; i < n; i += gridDim.x * 256) {
        float f = src[i];
        __nv_bfloat16 h = __float2bfloat16(f);
        hi[i] = h;
        lo[i] = __float2bfloat16(f - __bfloat162float(h));
    }
}

// v[(b*S+k)*E + e] -> vt16[(b*E+e)*S + k]
__global__ void transpose_f16_kernel(const float* __restrict__ v,
                                     __half* __restrict__ t16) {
    __shared__ float t[32][33];
    int bb = blockIdx.z;
    int k0 = blockIdx.x * 32, e0 = blockIdx.y * 32;
    int tx = threadIdx.x, ty = threadIdx.y;
    for (int i = ty; i < 32; i += 8)
        t[i][tx] = v[((long long)bb * S_ + k0 + i) * E_ + e0 + tx];
    __syncthreads();
    for (int i = ty; i < 32; i += 8) {
        long long o = ((long long)bb * E_ + e0 + i) * S_ + k0 + tx;
        t16[o] = __float2half(t[tx][i]);
    }
}

// softmax over the 16 heads per (b,q,k); writes fp16 attn
__global__ void softmax_heads_kernel(const float* __restrict__ sc,
                                     __half* __restrict__ a16) {
    long long p = (long long)blockIdx.x * 256 + threadIdx.x;  // over B*S*S
    int k = (int)(p & (S_ - 1));
    int q = (int)((p >> 11) & (S_ - 1));
    int b = (int)(p >> 22);
    long long base = (((long long)b * H_) * S_ + q) * S_ + k;
    float e[H_];
    float sum = 0.f;
#pragma unroll
    for (int h = 0; h < H_; h++) { e[h] = __expf(sc[base + (long long)h * SSLL]); sum += e[h]; }
    float inv = 1.f / sum;
#pragma unroll
    for (int h = 0; h < H_; h++)
        a16[base + (long long)h * SSLL] = __float2half(e[h] * inv);
}

// ---------------- mma.sync GEMM ----------------
// C[M,N] = scale*(A[M,K] @ B[N,K]^T) + bias.
// SPLIT=true: A/B are bf16 hi/lo pairs, 3-term MMA. SPLIT=false: fp16 single.
// Output: fp32 (Cf != null) or split-bf16 (Chi/Clo).
// 512 threads, 16 warps (8m x 2n), BM=128, BK=32, warp tile 16 x (BN/2).
// Batched via blockIdx.z: zb = z>>4, zh = z&15.
template <int BN, bool SPLIT>
__global__ __launch_bounds__(512)
void gemm_mma(const __nv_bfloat16* __restrict__ Ahi, const __nv_bfloat16* __restrict__ Alo,
              const __nv_bfloat16* __restrict__ Bhi, const __nv_bfloat16* __restrict__ Blo,
              const float* __restrict__ bias,
              float* __restrict__ Cf,
              __nv_bfloat16* __restrict__ Chi, __nv_bfloat16* __restrict__ Clo,
              int lda, int ldb, int ldc, int K, float scale,
              long long aB, long long aH, long long bB, long long bH,
              long long cB, long long cH)
{
    extern __shared__ char smem[];
    constexpr int ASZ = 128 * 80;                 // bytes per A matrix per stage
    constexpr int BSZ = BN * 80;
    constexpr int OFF_ALO = ASZ;
    constexpr int OFF_BHI = SPLIT ? 2 * ASZ : ASZ;
    constexpr int OFF_BLO = OFF_BHI + BSZ;
    constexpr int STAGE   = OFF_BHI + (SPLIT ? 2 : 1) * BSZ;
    constexpr int NT = BN / 16;                   // n8 tiles per warp

    const int tid  = threadIdx.x;
    const int lane = tid & 31;
    const int wid  = tid >> 5;
    const int wm   = wid & 7;                      // m warp 0..7
    const int wn   = wid >> 3;                     // n warp 0..1
    const int zb = blockIdx.z >> 4, zh = blockIdx.z & 15;
    const uint32_t sb = smem_u32(smem);

    const __nv_bfloat16* pAhi = Ahi + zb * aB + zh * aH + (long long)blockIdx.y * 128 * lda;
    const __nv_bfloat16* pAlo = SPLIT ? (Alo + zb * aB + zh * aH + (long long)blockIdx.y * 128 * lda) : nullptr;
    const __nv_bfloat16* pBhi = Bhi + zb * bB + zh * bH + (long long)blockIdx.x * BN * ldb;
    const __nv_bfloat16* pBlo = SPLIT ? (Blo + zb * bB + zh * bH + (long long)blockIdx.x * BN * ldb) : nullptr;

    // per-thread load slots
    const int arow = tid >> 2, ac = tid & 3;       // 512 threads -> 512 A chunks
    const int brow = tid >> 2, bc = tid & 3;       // B: BN*4 chunks

    auto load_stage = [&](int kb, int stg) {
        uint32_t s0 = sb + stg * STAGE;
        {
            long long g = (long long)arow * lda + kb * 32 + ac * 8;
            uint32_t d = s0 + arow * 80 + ac * 16;
            cp16(d, pAhi + g);
            if (SPLIT) cp16(d + OFF_ALO, pAlo + g);
        }
        if (BN == 128 || tid < BN * 4) {
            long long g = (long long)brow * ldb + kb * 32 + bc * 8;
            uint32_t d = s0 + OFF_BHI + brow * 80 + bc * 16;
            cp16(d, pBhi + g);
            if (SPLIT) cp16(d + (OFF_BLO - OFF_BHI), pBlo + g);
        }
    };

    const int KI = K >> 5;
    load_stage(0, 0); cp_commit();
    load_stage(1, 1); cp_commit();

    float acc[NT][4];
#pragma unroll
    for (int t = 0; t < NT; t++)
#pragma unroll
        for (int i = 0; i < 4; i++) acc[t][i] = 0.f;

    // fragment address components (constant across k-loop)
    const int a_r = wm * 16 + (lane & 15);
    const int a_c = (lane >> 4) * 16;                       // bytes
    const int b_r = wn * (BN / 2) + (lane & 7) + ((lane >> 4) & 1) * 8;
    const int b_c = ((lane >> 3) & 1) * 16;                 // bytes

    for (int kb = 0; kb < KI; kb++) {
        cp_wait1();
        __syncthreads();
        const uint32_t s0 = sb + (kb & 1) * STAGE;
#pragma unroll
        for (int ks = 0; ks < 2; ks++) {
            const uint32_t koff = ks * 32;                  // bytes (16 bf16)
            uint32_t ah[4], bh[NT * 2];
            ldsm4(ah, s0 + a_r * 80 + a_c + koff);
#pragma unroll
            for (int t2 = 0; t2 < NT / 2; t2++) {
                uint32_t r4[4];
                ldsm4(r4, s0 + OFF_BHI + (b_r + t2 * 16) * 80 + b_c + koff);
                bh[t2*4+0] = r4[0]; bh[t2*4+1] = r4[1]; bh[t2*4+2] = r4[2]; bh[t2*4+3] = r4[3];
            }
            if (SPLIT) {
#pragma unroll
                for (int t = 0; t < NT; t++) mma_bf16(acc[t], ah, &bh[t * 2]);
                uint32_t bl[NT * 2];
#pragma unroll
                for (int t2 = 0; t2 < NT / 2; t2++) {
                    uint32_t r4[4];
                    ldsm4(r4, s0 + OFF_BLO + (b_r + t2 * 16) * 80 + b_c + koff);
                    bl[t2*4+0] = r4[0]; bl[t2*4+1] = r4[1]; bl[t2*4+2] = r4[2]; bl[t2*4+3] = r4[3];
                }
#pragma unroll
                for (int t = 0; t < NT; t++) mma_bf16(acc[t], ah, &bl[t * 2]);
                uint32_t al[4];
                ldsm4(al, s0 + OFF_ALO + a_r * 80 + a_c + koff);
#pragma unroll
                for (int t = 0; t < NT; t++) mma_bf16(acc[t], al, &bh[t * 2]);
            } else {
#pragma unroll
                for (int t = 0; t < NT; t++) mma_f16(acc[t], ah, &bh[t * 2]);
            }
        }
        __syncthreads();
        if (kb + 2 < KI) load_stage(kb + 2, kb & 1);
        cp_commit();
    }

    // ---------------- epilogue ----------------
    const int mrow = blockIdx.y * 128 + wm * 16 + (lane >> 2);
    const int ncol0 = blockIdx.x * BN + wn * (BN / 2);
    const long long cb = zb * cB + zh * cH;
#pragma unroll
    for (int t = 0; t < NT; t++) {
        const int col = ncol0 + t * 8 + (lane & 3) * 2;
        float v0 = acc[t][0] * scale, v1 = acc[t][1] * scale;
        float v2 = acc[t][2] * scale, v3 = acc[t][3] * scale;
        if (bias) {
            float b0 = __ldg(&bias[col]), b1 = __ldg(&bias[col + 1]);
            v0 += b0; v1 += b1; v2 += b0; v3 += b1;
        }
        if (Cf) {
            *(float2*)(Cf + cb + (long long)mrow * ldc + col)       = make_float2(v0, v1);
            *(float2*)(Cf + cb + (long long)(mrow + 8) * ldc + col) = make_float2(v2, v3);
        } else {
            __nv_bfloat16 h0 = __float2bfloat16(v0), h1 = __float2bfloat16(v1);
            __nv_bfloat16 h2 = __float2bfloat16(v2), h3 = __float2bfloat16(v3);
            __nv_bfloat162 hp0; hp0.x = h0; hp0.y = h1;
            __nv_bfloat162 hp1; hp1.x = h2; hp1.y = h3;
            __nv_bfloat162 lp0; lp0.x = __float2bfloat16(v0 - __bfloat162float(h0));
                                lp0.y = __float2bfloat16(v1 - __bfloat162float(h1));
            __nv_bfloat162 lp1; lp1.x = __float2bfloat16(v2 - __bfloat162float(h2));
                                lp1.y = __float2bfloat16(v3 - __bfloat162float(h3));
            *(__nv_bfloat162*)(Chi + cb + (long long)mrow * ldc + col)       = hp0;
            *(__nv_bfloat162*)(Chi + cb + (long long)(mrow + 8) * ldc + col) = hp1;
            *(__nv_bfloat162*)(Clo + cb + (long long)mrow * ldc + col)       = lp0;
            *(__nv_bfloat162*)(Clo + cb + (long long)(mrow + 8) * ldc + col) = lp1;
        }
    }
}

// ---------------- launch ----------------
extern "C" void kernel_launch(void* const* d_in, const int* in_sizes, int n_in,
                              void* d_out, int out_size)
{
    const float* x  = (const float*)d_in[0];
    const float* Wq = (const float*)d_in[1];
    const float* bq = (const float*)d_in[2];
    const float* Wk = (const float*)d_in[3];
    const float* bk = (const float*)d_in[4];
    const float* Wv = (const float*)d_in[5];
    const float* bv = (const float*)d_in[6];
    const float* Wo = (const float*)d_in[7];
    const float* bo = (const float*)d_in[8];
    float* out = (float*)d_out;

    __nv_bfloat16 *xhi, *xlo, *whi, *wlo, *qhi, *qlo, *khi, *klo, *chi, *clo;
    __half *vt16, *a16;
    float *vf, *sc;
    cudaGetSymbolAddress((void**)&xhi, g_xhi);  cudaGetSymbolAddress((void**)&xlo, g_xlo);
    cudaGetSymbolAddress((void**)&whi, g_whi);  cudaGetSymbolAddress((void**)&wlo, g_wlo);
    cudaGetSymbolAddress((void**)&qhi, g_qhi);  cudaGetSymbolAddress((void**)&qlo, g_qlo);
    cudaGetSymbolAddress((void**)&khi, g_khi);  cudaGetSymbolAddress((void**)&klo, g_klo);
    cudaGetSymbolAddress((void**)&vf,  g_vf);
    cudaGetSymbolAddress((void**)&vt16, g_vt16);
    cudaGetSymbolAddress((void**)&sc,  g_sc);
    cudaGetSymbolAddress((void**)&a16, g_a16);
    cudaGetSymbolAddress((void**)&chi, g_chi);  cudaGetSymbolAddress((void**)&clo, g_clo);

    constexpr int SMEM_SPLIT = 2 * (2 * 128 * 80 + 2 * 128 * 80);  // 81920
    constexpr int SMEM_PV    = 2 * (128 * 80 + 64 * 80);           // 30720
    cudaFuncSetAttribute(gemm_mma<128, true>, cudaFuncAttributeMaxDynamicSharedMemorySize, SMEM_SPLIT);
    cudaFuncSetAttribute(gemm_mma<64, false>, cudaFuncAttributeMaxDynamicSharedMemorySize, SMEM_PV);

    const int EE = E_ * E_;

    // 1) split fp32 -> bf16 hi/lo
    split_kernel<<<2048, 256>>>(x,  xhi, xlo, NTOK * E_);
    split_kernel<<<1024, 256>>>(Wq, whi + 0 * EE, wlo + 0 * EE, EE);
    split_kernel<<<1024, 256>>>(Wk, whi + 1 * EE, wlo + 1 * EE, EE);
    split_kernel<<<1024, 256>>>(Wv, whi + 2 * EE, wlo + 2 * EE, EE);
    split_kernel<<<1024, 256>>>(Wo, whi + 3 * EE, wlo + 3 * EE, EE);

    // 2) projections
    dim3 gp(E_ / 128, NTOK / 128, 1);  // (8, 32)
    gemm_mma<128, true><<<gp, 512, SMEM_SPLIT>>>(xhi, xlo, whi + 0 * EE, wlo + 0 * EE, bq,
        nullptr, qhi, qlo, E_, E_, E_, E_, 1.f, 0, 0, 0, 0, 0, 0);
    gemm_mma<128, true><<<gp, 512, SMEM_SPLIT>>>(xhi, xlo, whi + 1 * EE, wlo + 1 * EE, bk,
        nullptr, khi, klo, E_, E_, E_, E_, 1.f, 0, 0, 0, 0, 0, 0);
    gemm_mma<128, true><<<gp, 512, SMEM_SPLIT>>>(xhi, xlo, whi + 2 * EE, wlo + 2 * EE, bv,
        vf, nullptr, nullptr, E_, E_, E_, E_, 1.f, 0, 0, 0, 0, 0, 0);

    // 3) transpose v -> vt16[b][e][k]
    transpose_f16_kernel<<<dim3(S_ / 32, E_ / 32, B_), dim3(32, 8)>>>(vf, vt16);

    // 4) scores[b,h,q,k] = (q.k)/8, batched z = b*16+h, K=64
    gemm_mma<128, true><<<dim3(S_ / 128, S_ / 128, B_ * H_), 512, SMEM_SPLIT>>>(
        qhi, qlo, khi, klo, nullptr, sc, nullptr, nullptr,
        E_, E_, S_, D_, 0.125f,
        (long long)S_ * E_, 64LL, (long long)S_ * E_, 64LL,
        (long long)H_ * SSLL, SSLL);

    // 5) softmax over heads -> fp16 attn
    softmax_heads_kernel<<<(unsigned)(B_ * SSLL / 256), 256>>>(sc, a16);

    // 6) ctx[b,q,h*64+d] = attn @ vt^T (fp16, single), out split-bf16
    gemm_mma<64, false><<<dim3(1, S_ / 128, B_ * H_), 512, SMEM_PV>>>(
        (const __nv_bfloat16*)a16, nullptr, (const __nv_bfloat16*)vt16, nullptr,
        nullptr, nullptr, chi, clo,
        S_, S_, E_, S_, 1.f,
        (long long)H_ * SSLL, SSLL, (long long)E_ * S_, 64LL * S_,
        (long long)S_ * E_, 64LL);

    // 7) output projection -> d_out (fp32)
    gemm_mma<128, true><<<gp, 512, SMEM_SPLIT>>>(chi, clo, whi + 3 * EE, wlo + 3 * EE, bo,
        out, nullptr, nullptr, E_, E_, E_, E_, 1.f, 0, 0, 0, 0, 0, 0);
}